// round 16
// baseline (speedup 1.0000x reference)
#include <cuda_runtime.h>
#include <cuda_bf16.h>
#include <cstdint>
#include <cstddef>

// ---------------------------------------------------------------------------
// Word2vec NCE forward, fused single-kernel edition (v6).
//   out[0 .. BATCH*EMB) = embeddings[inputs]   (f32, exact gather)
//   out[BATCH*EMB]      = nce_cost
//
// ONE kernel, grid 128 x 1024 threads (32 warps, r15 GEMM shape). Per block:
//   A: gather own 128 embed rows -> out (f32) + smem A (bf16 swizzled)
//   true-logits: 4 rows/warp, f32, registers + smem A (warp-local, syncwarp)
//   B: gather ncw[sids] directly -> smem B (L2-resident after first wave)
//   soff; syncthreads; 32-warp HMMA 128x256x256 (4m x 8n, 32x32 tiles);
//   batched-log softplus epilogue; partials + last-block finalize.
// No g_ab / g_wtb intermediates: saves 16 MB of DRAM round-trip + a launch.
// ---------------------------------------------------------------------------

namespace {
constexpr int VOCAB = 100000;
constexpr int EMB   = 256;
constexpr int NS    = 256;
constexpr int BATCH = 16384;
constexpr int TB    = 128;               // batch rows per block
constexpr int NBLK  = BATCH / TB;        // 128 blocks
constexpr int NTHR  = 1024;              // 32 warps

// smem byte map
constexpr int SM_A    = 0;               // A: 128 x 256 bf16 = 64 KB (512B pitch, swizzled)
constexpr int SM_B    = 65536;           // B: 256 x 256 bf16 = 128 KB
constexpr int SM_SOFF = 196608;          // soff[256] f32
constexpr int SM_WSUM = 197632;          // 32 warp partials
constexpr int SM_TOT  = 197632 + 192;
}

__device__ float    g_partial[NBLK];
__device__ unsigned g_done;              // static-init 0; reset after use

// ---------------------------------------------------------------------------
__device__ __forceinline__ long long load_id(const void* p, int i, int is64) {
    return is64 ? ((const long long*)p)[i] : (long long)((const int*)p)[i];
}
__device__ __forceinline__ int detect_is64(const void* p) {
    const int* q = (const int*)p;
    int z = 0;
    #pragma unroll
    for (int i = 0; i < 16; i++) z |= q[2 * i + 1];
    return (z == 0) ? 1 : 0;
}
__device__ __forceinline__ uint32_t smem_u32(const void* p) {
    uint32_t a;
    asm("{ .reg .u64 t; cvta.to.shared.u64 t, %1; cvt.u32.u64 %0, t; }"
        : "=r"(a) : "l"(p));
    return a;
}
// [row][256 bf16] tile, 512B pitch, 16B chunks XOR-swizzled by row&7
__device__ __forceinline__ uint32_t t_sw(int row, int chunk) {
    return (uint32_t)row * 512u + (uint32_t)(((chunk ^ (row & 7)) & 31) << 4);
}
__device__ __forceinline__ void ldsm_x4(uint32_t addr, uint32_t* r) {
    asm volatile("ldmatrix.sync.aligned.m8n8.x4.shared.b16 {%0,%1,%2,%3}, [%4];"
        : "=r"(r[0]), "=r"(r[1]), "=r"(r[2]), "=r"(r[3]) : "r"(addr));
}
__device__ __forceinline__ void mma_bf16(float* c, const uint32_t* a,
                                         const uint32_t* b) {
    asm volatile(
        "mma.sync.aligned.m16n8k16.row.col.f32.bf16.bf16.f32 "
        "{%0,%1,%2,%3}, {%4,%5,%6,%7}, {%8,%9}, {%0,%1,%2,%3};"
        : "+f"(c[0]), "+f"(c[1]), "+f"(c[2]), "+f"(c[3])
        : "r"(a[0]), "r"(a[1]), "r"(a[2]), "r"(a[3]), "r"(b[0]), "r"(b[1]));
}
__device__ __forceinline__ float softplus_neg(float ax) {
    return __logf(1.0f + __expf(-ax));   // log1p(exp(-ax)), ax >= 0
}
__device__ __forceinline__ uint4 pack_bf16x8(float4 v0, float4 v1) {
    __nv_bfloat162 p0 = __floats2bfloat162_rn(v0.x, v0.y);
    __nv_bfloat162 p1 = __floats2bfloat162_rn(v0.z, v0.w);
    __nv_bfloat162 p2 = __floats2bfloat162_rn(v1.x, v1.y);
    __nv_bfloat162 p3 = __floats2bfloat162_rn(v1.z, v1.w);
    uint4 u;
    u.x = *(uint32_t*)&p0;
    u.y = *(uint32_t*)&p1;
    u.z = *(uint32_t*)&p2;
    u.w = *(uint32_t*)&p3;
    return u;
}

// ---------------------------------------------------------------------------
__global__ void __launch_bounds__(NTHR, 1)
fused_kernel(const float* __restrict__ emb, const float* __restrict__ ncw,
             const float* __restrict__ ncb, const void* __restrict__ inputs,
             const void* __restrict__ labels, const void* __restrict__ sids,
             float* __restrict__ out)
{
    extern __shared__ __align__(1024) char smem[];
    const uint32_t smb = smem_u32(smem);
    const int tid  = threadIdx.x;
    const int wid  = tid >> 5;
    const int lane = tid & 31;
    const int b0   = blockIdx.x * TB;
    const float INVL = 1.0f / logf((float)VOCAB + 1.0f);

    const float4* emb4 = (const float4*)emb;
    const float4* ncw4 = (const float4*)ncw;
    float4*       out4 = (float4*)out;

    // ---- Phase A: embed gather -> out (f32) + smem A (bf16, swizzled)
    // 8 threads per row, each covers 32 k (8 float4), MLP 8.
    {
        const int is64 = detect_is64(inputs);
        const int r    = tid >> 3;               // 0..127
        const int part = tid & 7;                // k base = part*32
        long long g = load_id(inputs, b0 + r, is64);
        const float4* src = emb4 + (size_t)g * 64 + part * 8;
        float4*       dst = out4 + (size_t)(b0 + r) * 64 + part * 8;
        float4 v[8];
        #pragma unroll
        for (int i = 0; i < 8; i++) v[i] = src[i];
        #pragma unroll
        for (int i = 0; i < 8; i += 2) {
            dst[i]     = v[i];
            dst[i + 1] = v[i + 1];
            uint4 u = pack_bf16x8(v[i], v[i + 1]);
            *(uint4*)(smem + SM_A + t_sw(r, part * 4 + (i >> 1))) = u;
        }
    }
    __syncwarp();

    // ---- Phase B: true-logit xent, warp wid owns rows 4*wid .. +3
    // (exactly the rows this warp just wrote to smem A)
    float tsum = 0.0f;
    {
        const int is64l = detect_is64(labels);
        long long labs[4];
        float4 w0[4], w1[4];
        float  bb[4];
        #pragma unroll
        for (int rr = 0; rr < 4; rr++)
            labs[rr] = load_id(labels, b0 + wid * 4 + rr, is64l);
        #pragma unroll
        for (int rr = 0; rr < 4; rr++) {
            w0[rr] = ncw4[(size_t)labs[rr] * 64 + lane * 2];
            w1[rr] = ncw4[(size_t)labs[rr] * 64 + lane * 2 + 1];
            bb[rr] = ncb[labs[rr]];
        }
        #pragma unroll
        for (int rr = 0; rr < 4; rr++) {
            int r = wid * 4 + rr;
            uint4 eu = *(const uint4*)(smem + SM_A + t_sw(r, lane));
            float2 e0 = __bfloat1622float2(*(__nv_bfloat162*)&eu.x);
            float2 e1 = __bfloat1622float2(*(__nv_bfloat162*)&eu.y);
            float2 e2 = __bfloat1622float2(*(__nv_bfloat162*)&eu.z);
            float2 e3 = __bfloat1622float2(*(__nv_bfloat162*)&eu.w);
            float d = e0.x * w0[rr].x;
            d = fmaf(e0.y, w0[rr].y, d); d = fmaf(e1.x, w0[rr].z, d);
            d = fmaf(e1.y, w0[rr].w, d); d = fmaf(e2.x, w1[rr].x, d);
            d = fmaf(e2.y, w1[rr].y, d); d = fmaf(e3.x, w1[rr].z, d);
            d = fmaf(e3.y, w1[rr].w, d);
            #pragma unroll
            for (int o = 16; o > 0; o >>= 1)
                d += __shfl_xor_sync(0xffffffffu, d, o);
            if (lane == 0) {
                float fl = (float)labs[rr];
                float p  = (logf(fl + 2.0f) - logf(fl + 1.0f)) * INVL;
                float tl = d + bb[rr] - logf((float)NS * p);
                tsum += fmaxf(tl, 0.0f) - tl + softplus_neg(fabsf(tl));
            }
        }
    }

    // ---- Phase C: B gather: ncw[sids[s]] -> smem B (bf16, swizzled)
    // 4 threads per s-row, each covers 64 k (16 float4). L2-hot after wave 1.
    {
        const int is64s = detect_is64(sids);
        const int s  = tid >> 2;                 // 0..255
        const int kq = (tid & 3) * 16;           // float4 base
        long long sid = load_id(sids, s, is64s);
        const float4* bsrc = ncw4 + (size_t)sid * 64 + kq;
        #pragma unroll
        for (int i = 0; i < 16; i += 2) {
            float4 v0 = bsrc[i];
            float4 v1 = bsrc[i + 1];
            uint4 u = pack_bf16x8(v0, v1);
            *(uint4*)(smem + SM_B + t_sw(s, (tid & 3) * 8 + (i >> 1))) = u;
        }

        // ---- Phase D: sampled-logit offsets
        if (tid < NS) {
            long long id = load_id(sids, tid, is64s);
            float fid = (float)id;
            float p = (logf(fid + 2.0f) - logf(fid + 1.0f)) * INVL;
            ((float*)(smem + SM_SOFF))[tid] = ncb[id] - logf((float)NS * p);
        }
    }

    __syncthreads();

    // ---- Phase E: HMMA GEMM 128x256x256, warp grid 4m x 8n, tile 32x32
    const int wm = wid & 3;
    const int wn = wid >> 2;
    float acc[2][4][4];
    #pragma unroll
    for (int mt = 0; mt < 2; mt++)
        #pragma unroll
        for (int nt = 0; nt < 4; nt++)
            #pragma unroll
            for (int j = 0; j < 4; j++) acc[mt][nt][j] = 0.0f;

    const int amat  = lane >> 3;
    const int arow0 = wm * 32 + ((amat & 1) << 3) + (lane & 7);
    const int arow1 = arow0 + 16;
    const int aext  = amat >> 1;
    const uint32_t abase0 = smb + SM_A + (uint32_t)arow0 * 512u;
    const uint32_t abase1 = smb + SM_A + (uint32_t)arow1 * 512u;
    const int axor0 = arow0 & 7, axor1 = arow1 & 7;

    const int bg  = lane >> 3;
    const int bkh = bg & 1;
    int browp[2];
    #pragma unroll
    for (int ntp = 0; ntp < 2; ntp++)
        browp[ntp] = wn * 32 + (ntp * 2 + (bg >> 1)) * 8 + (lane & 7);

    #pragma unroll
    for (int ks = 0; ks < 16; ks++) {
        uint32_t a0[4], a1[4], b0f[4], b1f[4];
        int ac = ks * 2 + aext;
        ldsm_x4(abase0 + (uint32_t)(((ac ^ axor0) & 31) << 4), a0);
        ldsm_x4(abase1 + (uint32_t)(((ac ^ axor1) & 31) << 4), a1);
        int bc = ks * 2 + bkh;
        ldsm_x4(smb + SM_B + t_sw(browp[0], bc), b0f);
        ldsm_x4(smb + SM_B + t_sw(browp[1], bc), b1f);

        mma_bf16(acc[0][0], a0, b0f);
        mma_bf16(acc[1][0], a1, b0f);
        mma_bf16(acc[0][1], a0, b0f + 2);
        mma_bf16(acc[1][1], a1, b0f + 2);
        mma_bf16(acc[0][2], a0, b1f);
        mma_bf16(acc[1][2], a1, b1f);
        mma_bf16(acc[0][3], a0, b1f + 2);
        mma_bf16(acc[1][3], a1, b1f + 2);
    }

    // ---- Phase F: epilogue: relu-sum + batched-log softplus
    const float* soff = (const float*)(smem + SM_SOFF);
    float ssum = tsum;
    {
        const int colb = wn * 32 + ((lane & 3) << 1);
        #pragma unroll
        for (int nt = 0; nt < 4; nt++) {
            float s0 = soff[colb + nt * 8];
            float s1 = soff[colb + nt * 8 + 1];
            float prod = 1.0f;
            #pragma unroll
            for (int mt = 0; mt < 2; mt++) {
                float l0 = acc[mt][nt][0] + s0;
                float l1 = acc[mt][nt][1] + s1;
                float l2 = acc[mt][nt][2] + s0;
                float l3 = acc[mt][nt][3] + s1;
                ssum += fmaxf(l0, 0.0f) + fmaxf(l1, 0.0f)
                      + fmaxf(l2, 0.0f) + fmaxf(l3, 0.0f);
                float t0 = 1.0f + __expf(-fabsf(l0));
                float t1 = 1.0f + __expf(-fabsf(l1));
                float t2 = 1.0f + __expf(-fabsf(l2));
                float t3 = 1.0f + __expf(-fabsf(l3));
                prod *= (t0 * t1) * (t2 * t3);
            }
            ssum += __logf(prod);
        }
    }

    // ---- reduce: warp -> block -> global
    #pragma unroll
    for (int o = 16; o > 0; o >>= 1) ssum += __shfl_xor_sync(0xffffffffu, ssum, o);
    if (lane == 0) ((float*)(smem + SM_WSUM))[wid] = ssum;
    __syncthreads();

    __shared__ int s_last;
    if (tid == 0) {
        float t = 0.0f;
        #pragma unroll
        for (int i = 0; i < 32; i++) t += ((float*)(smem + SM_WSUM))[i];
        g_partial[blockIdx.x] = t;
        __threadfence();
        unsigned cnt = atomicAdd(&g_done, 1u);
        s_last = (cnt == (unsigned)(NBLK - 1)) ? 1 : 0;
    }
    __syncthreads();

    if (s_last && wid == 0) {
        float s = 0.0f;
        #pragma unroll
        for (int i = 0; i < NBLK / 32; i++) s += g_partial[lane + i * 32];
        #pragma unroll
        for (int o = 16; o > 0; o >>= 1) s += __shfl_xor_sync(0xffffffffu, s, o);
        if (lane == 0) {
            out[(size_t)BATCH * EMB] = s * (1.0f / (float)BATCH);
            g_done = 0u;                     // reset for next graph replay
            __threadfence();
        }
    }
}

// ---------------------------------------------------------------------------
extern "C" void kernel_launch(void* const* d_in, const int* in_sizes, int n_in,
                              void* d_out, int out_size) {
    const float* emb    = (const float*)d_in[0];
    const float* ncw    = (const float*)d_in[1];
    const float* ncb    = (const float*)d_in[2];
    const void*  inputs = d_in[3];
    const void*  labels = d_in[4];
    const void*  sids   = d_in[5];
    float* out = (float*)d_out;

    cudaFuncSetAttribute(fused_kernel,
                         cudaFuncAttributeMaxDynamicSharedMemorySize, SM_TOT);

    fused_kernel<<<NBLK, NTHR, SM_TOT>>>(emb, ncw, ncb, inputs, labels, sids, out);
}